// round 14
// baseline (speedup 1.0000x reference)
#include <cuda_runtime.h>

// out[r] = (sum over 1024 elems of row r of x) * (sum of coeffs)
// x: (16, 4096, 1024) fp32 -> 65536 rows of 1024
// coeffs: (10, 1) fp32
//
// FINAL (R9 config, best measured 41.44us wall / 6.75 TB/s):
// - one warp per row, fire-and-exit (8192 blocks x 256 threads)
// - four 256-bit ld.global.nc.L2::evict_first.v8.b32 loads per lane,
//   all in ONE asm block with 32 distinct output registers -> ptxas
//   cannot serialize them; guaranteed per-lane MLP = 4 x 32B
// - butterfly warp reduction, lane 0 scales by sum(coeffs) and stores
//
// Measured DRAM 82-85% of 8TB/s spec across runs == the sm_103a LTS
// chip-throughput cap (~6300 B/cyc, path-independent per B300 uarch
// measurements). TMA / cp.async / persistence / wider per-warp tiles
// were all tested and are neutral-to-negative: this access pattern is
// at its architectural roofline.

__global__ __launch_bounds__(256) void spline_rowsum_v8mlp_kernel(
    const float* __restrict__ x,
    const float* __restrict__ coeffs,
    int n_coeffs,
    float* __restrict__ out,
    int nrows)
{
    int gwarp = (blockIdx.x * blockDim.x + threadIdx.x) >> 5;
    int lane  = threadIdx.x & 31;
    if (gwarp >= nrows) return;

    const float* row = x + (size_t)gwarp * 1024 + lane * 8;

    float f0, f1, f2, f3, f4, f5, f6, f7,
          f8, f9, f10, f11, f12, f13, f14, f15,
          f16, f17, f18, f19, f20, f21, f22, f23,
          f24, f25, f26, f27, f28, f29, f30, f31;

    // 4 x 256-bit loads, one asm block -> 32 live dest regs, issued
    // back-to-back. Offsets in bytes: 256 floats = 1024B apart.
    asm volatile(
        "ld.global.nc.L2::evict_first.v8.b32 {%0,%1,%2,%3,%4,%5,%6,%7}, [%32];\n\t"
        "ld.global.nc.L2::evict_first.v8.b32 {%8,%9,%10,%11,%12,%13,%14,%15}, [%32+1024];\n\t"
        "ld.global.nc.L2::evict_first.v8.b32 {%16,%17,%18,%19,%20,%21,%22,%23}, [%32+2048];\n\t"
        "ld.global.nc.L2::evict_first.v8.b32 {%24,%25,%26,%27,%28,%29,%30,%31}, [%32+3072];"
        : "=f"(f0),  "=f"(f1),  "=f"(f2),  "=f"(f3),
          "=f"(f4),  "=f"(f5),  "=f"(f6),  "=f"(f7),
          "=f"(f8),  "=f"(f9),  "=f"(f10), "=f"(f11),
          "=f"(f12), "=f"(f13), "=f"(f14), "=f"(f15),
          "=f"(f16), "=f"(f17), "=f"(f18), "=f"(f19),
          "=f"(f20), "=f"(f21), "=f"(f22), "=f"(f23),
          "=f"(f24), "=f"(f25), "=f"(f26), "=f"(f27),
          "=f"(f28), "=f"(f29), "=f"(f30), "=f"(f31)
        : "l"(row));

    float s0 = ((f0  + f1)  + (f2  + f3))  + ((f4  + f5)  + (f6  + f7));
    float s1 = ((f8  + f9)  + (f10 + f11)) + ((f12 + f13) + (f14 + f15));
    float s2 = ((f16 + f17) + (f18 + f19)) + ((f20 + f21) + (f22 + f23));
    float s3 = ((f24 + f25) + (f26 + f27)) + ((f28 + f29) + (f30 + f31));
    float s = (s0 + s1) + (s2 + s3);

    // butterfly warp reduction
#pragma unroll
    for (int off = 16; off; off >>= 1)
        s += __shfl_xor_sync(0xFFFFFFFFu, s, off);

    if (lane == 0) {
        float c = 0.0f;
        for (int i = 0; i < n_coeffs; i++) c += coeffs[i];
        out[gwarp] = s * c;
    }
}

extern "C" void kernel_launch(void* const* d_in, const int* in_sizes, int n_in,
                              void* d_out, int out_size)
{
    const float* x      = (const float*)d_in[0];
    const float* coeffs = (const float*)d_in[1];
    float* out          = (float*)d_out;

    int nrows    = in_sizes[0] / 1024;   // 65536
    int n_coeffs = in_sizes[1];          // 10

    // 8 warps (rows) per 256-thread block
    int blocks = (nrows + 7) / 8;        // 8192
    spline_rowsum_v8mlp_kernel<<<blocks, 256>>>(x, coeffs, n_coeffs, out, nrows);
}

// round 15
// speedup vs baseline: 1.0153x; 1.0153x over previous
#include <cuda_runtime.h>

// out[r] = (sum over 1024 elems of row r of x) * (sum of coeffs)
// x: (16, 4096, 1024) fp32 -> 65536 rows of 1024
// coeffs: (10, 1) fp32
//
// R9 load path (best measured, LTS-cap-bound: ~6.6-6.75 TB/s):
//   one warp per row, four 256-bit ld.global.nc.L2::evict_first.v8.b32
//   per lane in ONE asm block with 32 distinct output registers
//   (guaranteed per-lane MLP = 4 x 32B).
// New this round: epilogue trim. coeffs summed via one predicated
// parallel load per lane + the same butterfly that reduces the row sum
// (packed float2), replacing lane-0's serial 10-load loop (~400cyc tail).

__global__ __launch_bounds__(256) void spline_rowsum_v8mlp_kernel(
    const float* __restrict__ x,
    const float* __restrict__ coeffs,
    int n_coeffs,
    float* __restrict__ out,
    int nrows)
{
    int gwarp = (blockIdx.x * blockDim.x + threadIdx.x) >> 5;
    int lane  = threadIdx.x & 31;
    if (gwarp >= nrows) return;

    const float* row = x + (size_t)gwarp * 1024 + lane * 8;

    float f0, f1, f2, f3, f4, f5, f6, f7,
          f8, f9, f10, f11, f12, f13, f14, f15,
          f16, f17, f18, f19, f20, f21, f22, f23,
          f24, f25, f26, f27, f28, f29, f30, f31;

    // 4 x 256-bit loads, one asm block -> 32 live dest regs, issued
    // back-to-back. Offsets in bytes: 256 floats = 1024B apart.
    asm volatile(
        "ld.global.nc.L2::evict_first.v8.b32 {%0,%1,%2,%3,%4,%5,%6,%7}, [%32];\n\t"
        "ld.global.nc.L2::evict_first.v8.b32 {%8,%9,%10,%11,%12,%13,%14,%15}, [%32+1024];\n\t"
        "ld.global.nc.L2::evict_first.v8.b32 {%16,%17,%18,%19,%20,%21,%22,%23}, [%32+2048];\n\t"
        "ld.global.nc.L2::evict_first.v8.b32 {%24,%25,%26,%27,%28,%29,%30,%31}, [%32+3072];"
        : "=f"(f0),  "=f"(f1),  "=f"(f2),  "=f"(f3),
          "=f"(f4),  "=f"(f5),  "=f"(f6),  "=f"(f7),
          "=f"(f8),  "=f"(f9),  "=f"(f10), "=f"(f11),
          "=f"(f12), "=f"(f13), "=f"(f14), "=f"(f15),
          "=f"(f16), "=f"(f17), "=f"(f18), "=f"(f19),
          "=f"(f20), "=f"(f21), "=f"(f22), "=f"(f23),
          "=f"(f24), "=f"(f25), "=f"(f26), "=f"(f27),
          "=f"(f28), "=f"(f29), "=f"(f30), "=f"(f31)
        : "l"(row));

    // Parallel coeff gather: one predicated load per lane (n_coeffs=10
    // in practice; loop handles n_coeffs > 32 for safety). Hits L1/L2.
    float c = 0.0f;
    for (int i = lane; i < n_coeffs; i += 32)
        c += coeffs[i];

    float s0 = ((f0  + f1)  + (f2  + f3))  + ((f4  + f5)  + (f6  + f7));
    float s1 = ((f8  + f9)  + (f10 + f11)) + ((f12 + f13) + (f14 + f15));
    float s2 = ((f16 + f17) + (f18 + f19)) + ((f20 + f21) + (f22 + f23));
    float s3 = ((f24 + f25) + (f26 + f27)) + ((f28 + f29) + (f30 + f31));
    float s = (s0 + s1) + (s2 + s3);

    // Packed butterfly: reduce row sum and coeff sum together (5 shuffles)
    float2 sv = make_float2(s, c);
    unsigned long long pk = *reinterpret_cast<unsigned long long*>(&sv);
#pragma unroll
    for (int off = 16; off; off >>= 1) {
        unsigned long long other = __shfl_xor_sync(0xFFFFFFFFu, pk, off);
        float2 o = *reinterpret_cast<float2*>(&other);
        float2 t = *reinterpret_cast<float2*>(&pk);
        t.x += o.x; t.y += o.y;
        pk = *reinterpret_cast<unsigned long long*>(&t);
    }
    float2 tot = *reinterpret_cast<float2*>(&pk);

    if (lane == 0)
        out[gwarp] = tot.x * tot.y;
}

extern "C" void kernel_launch(void* const* d_in, const int* in_sizes, int n_in,
                              void* d_out, int out_size)
{
    const float* x      = (const float*)d_in[0];
    const float* coeffs = (const float*)d_in[1];
    float* out          = (float*)d_out;

    int nrows    = in_sizes[0] / 1024;   // 65536
    int n_coeffs = in_sizes[1];          // 10

    // 8 warps (rows) per 256-thread block
    int blocks = (nrows + 7) / 8;        // 8192
    spline_rowsum_v8mlp_kernel<<<blocks, 256>>>(x, coeffs, n_coeffs, out, nrows);
}

// round 16
// speedup vs baseline: 1.0232x; 1.0077x over previous
#include <cuda_runtime.h>

// out[r] = (sum over 1024 elems of row r of x) * (sum of coeffs)
// x: (16, 4096, 1024) fp32 -> 65536 rows of 1024
// coeffs: (10, 1) fp32
//
// FINAL. Best measured: ncu dur 39.97us, DRAM 86.0% (6812 GB/s) — at the
// sm_103a LTS chip-throughput cap (path-independent, ~6300 B/cyc band).
//
// Structure:
// - one warp per row, fire-and-exit (8192 blocks x 256 threads)
// - four 256-bit ld.global.nc.L2::evict_first.v8.b32 loads per lane in
//   ONE asm block with 32 distinct output registers -> ptxas cannot
//   serialize them; guaranteed per-lane MLP = 4 x 32B
// - coeffs gathered in parallel (one predicated load per lane) and
//   reduced together with the row sum in a single packed-float2
//   butterfly (5 shuffles total); lane 0 multiplies and stores
//
// Session evidence: persistence, 2-rows/warp, __ldcs, and 512-thread
// blocks all measured neutral-to-negative; v8+evict_first, forced-MLP,
// and the packed epilogue are the three real wins (43.1 -> 40.0 ncu).

__global__ __launch_bounds__(256) void spline_rowsum_v8mlp_kernel(
    const float* __restrict__ x,
    const float* __restrict__ coeffs,
    int n_coeffs,
    float* __restrict__ out,
    int nrows)
{
    int gwarp = (blockIdx.x * blockDim.x + threadIdx.x) >> 5;
    int lane  = threadIdx.x & 31;
    if (gwarp >= nrows) return;

    const float* row = x + (size_t)gwarp * 1024 + lane * 8;

    float f0, f1, f2, f3, f4, f5, f6, f7,
          f8, f9, f10, f11, f12, f13, f14, f15,
          f16, f17, f18, f19, f20, f21, f22, f23,
          f24, f25, f26, f27, f28, f29, f30, f31;

    // 4 x 256-bit loads, one asm block -> 32 live dest regs, issued
    // back-to-back. Offsets in bytes: 256 floats = 1024B apart.
    asm volatile(
        "ld.global.nc.L2::evict_first.v8.b32 {%0,%1,%2,%3,%4,%5,%6,%7}, [%32];\n\t"
        "ld.global.nc.L2::evict_first.v8.b32 {%8,%9,%10,%11,%12,%13,%14,%15}, [%32+1024];\n\t"
        "ld.global.nc.L2::evict_first.v8.b32 {%16,%17,%18,%19,%20,%21,%22,%23}, [%32+2048];\n\t"
        "ld.global.nc.L2::evict_first.v8.b32 {%24,%25,%26,%27,%28,%29,%30,%31}, [%32+3072];"
        : "=f"(f0),  "=f"(f1),  "=f"(f2),  "=f"(f3),
          "=f"(f4),  "=f"(f5),  "=f"(f6),  "=f"(f7),
          "=f"(f8),  "=f"(f9),  "=f"(f10), "=f"(f11),
          "=f"(f12), "=f"(f13), "=f"(f14), "=f"(f15),
          "=f"(f16), "=f"(f17), "=f"(f18), "=f"(f19),
          "=f"(f20), "=f"(f21), "=f"(f22), "=f"(f23),
          "=f"(f24), "=f"(f25), "=f"(f26), "=f"(f27),
          "=f"(f28), "=f"(f29), "=f"(f30), "=f"(f31)
        : "l"(row));

    // Parallel coeff gather: one predicated load per lane (n_coeffs=10
    // in practice; loop handles n_coeffs > 32 for safety). Hits L1/L2.
    float c = 0.0f;
    for (int i = lane; i < n_coeffs; i += 32)
        c += coeffs[i];

    float s0 = ((f0  + f1)  + (f2  + f3))  + ((f4  + f5)  + (f6  + f7));
    float s1 = ((f8  + f9)  + (f10 + f11)) + ((f12 + f13) + (f14 + f15));
    float s2 = ((f16 + f17) + (f18 + f19)) + ((f20 + f21) + (f22 + f23));
    float s3 = ((f24 + f25) + (f26 + f27)) + ((f28 + f29) + (f30 + f31));
    float s = (s0 + s1) + (s2 + s3);

    // Packed butterfly: reduce row sum and coeff sum together (5 shuffles)
    float2 sv = make_float2(s, c);
    unsigned long long pk = *reinterpret_cast<unsigned long long*>(&sv);
#pragma unroll
    for (int off = 16; off; off >>= 1) {
        unsigned long long other = __shfl_xor_sync(0xFFFFFFFFu, pk, off);
        float2 o = *reinterpret_cast<float2*>(&other);
        float2 t = *reinterpret_cast<float2*>(&pk);
        t.x += o.x; t.y += o.y;
        pk = *reinterpret_cast<unsigned long long*>(&t);
    }
    float2 tot = *reinterpret_cast<float2*>(&pk);

    if (lane == 0)
        out[gwarp] = tot.x * tot.y;
}

extern "C" void kernel_launch(void* const* d_in, const int* in_sizes, int n_in,
                              void* d_out, int out_size)
{
    const float* x      = (const float*)d_in[0];
    const float* coeffs = (const float*)d_in[1];
    float* out          = (float*)d_out;

    int nrows    = in_sizes[0] / 1024;   // 65536
    int n_coeffs = in_sizes[1];          // 10

    // 8 warps (rows) per 256-thread block
    int blocks = (nrows + 7) / 8;        // 8192
    spline_rowsum_v8mlp_kernel<<<blocks, 256>>>(x, coeffs, n_coeffs, out, nrows);
}